// round 6
// baseline (speedup 1.0000x reference)
#include <cuda_runtime.h>
#include <cuda_bf16.h>
#include <cfloat>
#include <cstdint>

// LossFun: loss = -sum over (b,l) of [argmax_v(scores)==target] * w * log(max score) / B
// scores: [B, L, V] float32, targets: [B, L] int32. B=8, L=2048, V=32000.
//
// Single fused kernel: per-row argmax (CTA per row), double atomic accumulate,
// last-arriving CTA finalizes the output and resets the globals (zero-init at
// module load; reset-after-read keeps every graph replay deterministic).
//
// Precision: picked = max of 32000 uniforms ~ (1 - 3e-5), so log(picked) ~ -3e-5.
// Accurate logf (not __logf) + double accumulator keep rel_err ~1e-7.

static constexpr int V_DIM   = 32000;
static constexpr int V_VEC4  = V_DIM / 4;   // 8000
static constexpr double INV_B = 1.0 / 8.0;
static constexpr float  BETA  = 2.0f;

__device__ double       g_acc;    // zero-initialized at module load
__device__ unsigned int g_done;   // zero-initialized at module load

__global__ __launch_bounds__(256, 8)
void lossfun_fused_kernel(const float* __restrict__ scores,
                          const int* __restrict__ targets,
                          float* __restrict__ out,
                          int rows)
{
    const int row = blockIdx.x;
    const float4* __restrict__ p =
        reinterpret_cast<const float4*>(scores + (size_t)row * V_DIM);

    float best = -FLT_MAX;
    int   bidx = 0x7FFFFFFF;

    // Coalesced strided float4 scan; first-index tiebreak on equal values.
    for (int i = threadIdx.x; i < V_VEC4; i += 256) {
        float4 v = __ldg(p + i);
        int base = i << 2;
        if (v.x > best || (v.x == best && base + 0 < bidx)) { best = v.x; bidx = base + 0; }
        if (v.y > best || (v.y == best && base + 1 < bidx)) { best = v.y; bidx = base + 1; }
        if (v.z > best || (v.z == best && base + 2 < bidx)) { best = v.z; bidx = base + 2; }
        if (v.w > best || (v.w == best && base + 3 < bidx)) { best = v.w; bidx = base + 3; }
    }

    // Warp reduce (value-max, lowest index on tie)
    #pragma unroll
    for (int o = 16; o > 0; o >>= 1) {
        float ov = __shfl_down_sync(0xFFFFFFFFu, best, o);
        int   oi = __shfl_down_sync(0xFFFFFFFFu, bidx, o);
        if (ov > best || (ov == best && oi < bidx)) { best = ov; bidx = oi; }
    }

    __shared__ float sv[8];
    __shared__ int   si[8];
    const int lane = threadIdx.x & 31;
    const int wid  = threadIdx.x >> 5;
    if (lane == 0) { sv[wid] = best; si[wid] = bidx; }
    __syncthreads();

    if (threadIdx.x == 0) {
        float fb = sv[0]; int fi = si[0];
        #pragma unroll
        for (int w = 1; w < 8; w++) {
            float ov = sv[w]; int oi = si[w];
            if (ov > fb || (ov == fb && oi < fi)) { fb = ov; fi = oi; }
        }
        int tgt = __ldg(targets + row);
        if (fi == tgt) {
            float w = (tgt == 0) ? 1.0f : BETA;
            atomicAdd(&g_acc, (double)(-w * logf(fb)));
        }

        // Make this CTA's contribution (if any) visible before signaling done.
        __threadfence();
        unsigned int prev = atomicAdd(&g_done, 1u);
        if (prev == (unsigned int)(rows - 1)) {
            // Last CTA: all g_acc adds are fenced-before their counter bumps,
            // and atomic RMWs on g_acc are globally coherent -> safe to read.
            double acc = atomicAdd(&g_acc, 0.0);
            out[0] = (float)(acc * INV_B);
            // Reset for the next graph replay (deterministic invariant).
            g_acc  = 0.0;
            g_done = 0u;
            __threadfence();
        }
    }
}

extern "C" void kernel_launch(void* const* d_in, const int* in_sizes, int n_in,
                              void* d_out, int out_size)
{
    const float* scores  = (const float*)d_in[0];
    const int*   targets = (const int*)d_in[1];
    float*       out     = (float*)d_out;

    const int rows = in_sizes[1];   // B * L = 16384

    lossfun_fused_kernel<<<rows, 256>>>(scores, targets, out, rows);
}

// round 7
// speedup vs baseline: 1.0264x; 1.0264x over previous
#include <cuda_runtime.h>
#include <cuda_bf16.h>
#include <cfloat>
#include <cstdint>

// LossFun: loss = -sum over (b,l) of [argmax_v(scores)==target] * w * log(max score) / B
// scores: [B, L, V] float32, targets: [B, L] int32. B=8, L=2048, V=32000.
//
// CTA per row. Scan uses an FMNMX-tree fast path (tile max), with a rare
// slow path resolving the argmax index only when the running best improves
// (~ln(n) times per thread). Strict '>' update + in-order resolution chain
// preserves first-index tiebreak (argmax semantics; duplicated maxima do
// occur at fp32 with 32000 uniforms/row).
//
// Precision: picked ~ (1 - 3e-5) so log(picked) ~ -3e-5: accurate logf +
// double accumulator required (rel_err ~1e-7).

static constexpr int V_DIM  = 32000;
static constexpr int V_VEC4 = V_DIM / 4;      // 8000
static constexpr double INV_B = 1.0 / 8.0;
static constexpr float  BETA  = 2.0f;

__device__ double g_acc;   // zero-init at module load; finalize resets per replay

__device__ __forceinline__ void tile_update(const float4& v, int base,
                                            float& best, int& bidx, float m)
{
    // called only when m > best already established is false -> we re-test here
    if (v.x == m && base + 0 < bidx) { bidx = base + 0; return; }
    if (v.y == m && base + 1 < bidx) { bidx = base + 1; return; }
    if (v.z == m && base + 2 < bidx) { bidx = base + 2; return; }
    if (v.w == m && base + 3 < bidx) { bidx = base + 3; return; }
}

__global__ __launch_bounds__(256, 4)
void lossfun_argmax_kernel(const float* __restrict__ scores,
                           const int* __restrict__ targets)
{
    const int tid = threadIdx.x;
    const int row = blockIdx.x;
    const float4* __restrict__ p =
        reinterpret_cast<const float4*>(scores + (size_t)row * V_DIM);

    float best = -FLT_MAX;
    int   bidx = 0x7FFFFFFF;

    // Main loop: 7 iterations x 4 coalesced float4 loads = 7168 vec4.
    #pragma unroll
    for (int k = 0; k < 7; k++) {
        const int i = tid + k * 1024;
        float4 a = __ldg(p + i);
        float4 b = __ldg(p + i + 256);
        float4 c = __ldg(p + i + 512);
        float4 d = __ldg(p + i + 768);

        float ma = fmaxf(fmaxf(a.x, a.y), fmaxf(a.z, a.w));
        float mb = fmaxf(fmaxf(b.x, b.y), fmaxf(b.z, b.w));
        float mc = fmaxf(fmaxf(c.x, c.y), fmaxf(c.z, c.w));
        float md = fmaxf(fmaxf(d.x, d.y), fmaxf(d.z, d.w));
        float m  = fmaxf(fmaxf(ma, mb), fmaxf(mc, md));

        if (m > best) {                 // rare: ~ln(#tiles) per thread
            best = m;
            bidx = 0x7FFFFFFF;
            // in-order resolution = first index of m within this tile
            if      (ma == m) tile_update(a, (i)          << 2, best, bidx, m);
            if (bidx == 0x7FFFFFFF && mb == m) tile_update(b, (i + 256) << 2, best, bidx, m);
            if (bidx == 0x7FFFFFFF && mc == m) tile_update(c, (i + 512) << 2, best, bidx, m);
            if (bidx == 0x7FFFFFFF && md == m) tile_update(d, (i + 768) << 2, best, bidx, m);
        }
    }

    // Epilogue: vec4 indices 7168..7999 (832 = 3*256 + 64).
    {
        const int i1 = 7168 + tid;
        const int i2 = 7424 + tid;
        const int i3 = 7680 + tid;
        float4 a = __ldg(p + i1);
        float4 b = __ldg(p + i2);
        float4 c = __ldg(p + i3);

        float ma = fmaxf(fmaxf(a.x, a.y), fmaxf(a.z, a.w));
        float mb = fmaxf(fmaxf(b.x, b.y), fmaxf(b.z, b.w));
        float mc = fmaxf(fmaxf(c.x, c.y), fmaxf(c.z, c.w));
        float m  = fmaxf(fmaxf(ma, mb), mc);

        if (m > best) {
            best = m;
            bidx = 0x7FFFFFFF;
            if      (ma == m) tile_update(a, i1 << 2, best, bidx, m);
            if (bidx == 0x7FFFFFFF && mb == m) tile_update(b, i2 << 2, best, bidx, m);
            if (bidx == 0x7FFFFFFF && mc == m) tile_update(c, i3 << 2, best, bidx, m);
        }

        if (tid < 64) {
            const int i4 = 7936 + tid;
            float4 d = __ldg(p + i4);
            float md = fmaxf(fmaxf(d.x, d.y), fmaxf(d.z, d.w));
            if (md > best) {
                best = md;
                bidx = 0x7FFFFFFF;
                tile_update(d, i4 << 2, best, bidx, md);
            }
        }
    }

    // Warp reduce (value-max, lowest index on tie)
    #pragma unroll
    for (int o = 16; o > 0; o >>= 1) {
        float ov = __shfl_down_sync(0xFFFFFFFFu, best, o);
        int   oi = __shfl_down_sync(0xFFFFFFFFu, bidx, o);
        if (ov > best || (ov == best && oi < bidx)) { best = ov; bidx = oi; }
    }

    __shared__ float sv[8];
    __shared__ int   si[8];
    const int lane = tid & 31;
    const int wid  = tid >> 5;
    if (lane == 0) { sv[wid] = best; si[wid] = bidx; }
    __syncthreads();

    if (tid == 0) {
        float fb = sv[0]; int fi = si[0];
        #pragma unroll
        for (int w = 1; w < 8; w++) {
            float ov = sv[w]; int oi = si[w];
            if (ov > fb || (ov == fb && oi < fi)) { fb = ov; fi = oi; }
        }
        int tgt = __ldg(targets + row);
        if (fi == tgt) {
            float w = (tgt == 0) ? 1.0f : BETA;
            atomicAdd(&g_acc, (double)(-w * logf(fb)));
        }
    }
}

__global__ void lossfun_finalize_kernel(float* __restrict__ out)
{
    out[0] = (float)(g_acc * INV_B);
    g_acc  = 0.0;   // restore invariant for next graph replay
}

extern "C" void kernel_launch(void* const* d_in, const int* in_sizes, int n_in,
                              void* d_out, int out_size)
{
    const float* scores  = (const float*)d_in[0];
    const int*   targets = (const int*)d_in[1];
    float*       out     = (float*)d_out;

    const int rows = in_sizes[1];   // B * L = 16384

    lossfun_argmax_kernel<<<rows, 256>>>(scores, targets);
    lossfun_finalize_kernel<<<1, 1>>>(out);
}